// round 1
// baseline (speedup 1.0000x reference)
#include <cuda_runtime.h>
#include <math.h>
#include <stdint.h>

// ---------------- problem caps (actual: B=64, P=8732, C=81, G=16) ------------
#define MAXB 64
#define MAXP 8732
#define MAXG 16
#define MAXBP (MAXB * MAXP)

// ---------------- scratch (no allocations allowed) ---------------------------
__device__ float  g_bg[MAXBP];     // bg_loss per (b,p); -inf for positives
__device__ int    g_match[MAXBP];  // matched gt index per prior
__device__ float  g_mval[MAXBP];   // matched IoU value (2.0 for forced)
__device__ int    g_bestp[MAXB * MAXG];
__device__ int    g_npos[MAXB];
__device__ double g_boxsum;
__device__ double g_cesum;

// ---------------- helpers ----------------------------------------------------
__device__ __forceinline__ float iou_f(float ax1, float ay1, float ax2, float ay2,
                                       float bx1, float by1, float bx2, float by2) {
    float lx = fmaxf(ax1, bx1), ly = fmaxf(ay1, by1);
    float rx = fminf(ax2, bx2), ry = fminf(ay2, by2);
    float w = fmaxf(rx - lx, 0.0f), h = fmaxf(ry - ly, 0.0f);
    float inter = w * h;
    float aa = (ax2 - ax1) * (ay2 - ay1);
    float ab = (bx2 - bx1) * (by2 - by1);
    return inter / (aa + ab - inter);
}

__device__ __forceinline__ unsigned f2k(float f) {
    unsigned b = __float_as_uint(f);
    return (b & 0x80000000u) ? ~b : (b | 0x80000000u);
}
__device__ __forceinline__ float k2f(unsigned k) {
    unsigned b = (k & 0x80000000u) ? (k ^ 0x80000000u) : ~k;
    return __uint_as_float(b);
}

// ---------------- kernel 0: zero accumulators --------------------------------
__global__ void k_init(int B) {
    int t = threadIdx.x;
    if (t < B) g_npos[t] = 0;
    if (t == 0) { g_boxsum = 0.0; g_cesum = 0.0; }
}

// ---------------- kernel 1: per-prior max/argmax over GTs --------------------
__global__ void k_match_rows(const float* __restrict__ priors,
                             const float* __restrict__ gt_boxes,
                             int B, int P, int G) {
    int idx = blockIdx.x * blockDim.x + threadIdx.x;
    if (idx >= B * P) return;
    int b = idx / P, p = idx - b * P;

    float cx = priors[p * 4 + 0], cy = priors[p * 4 + 1];
    float w  = priors[p * 4 + 2], h  = priors[p * 4 + 3];
    float px1 = cx - w * 0.5f, py1 = cy - h * 0.5f;
    float px2 = cx + w * 0.5f, py2 = cy + h * 0.5f;

    const float* gt = gt_boxes + (size_t)b * G * 4;
    float bv = -1.0f; int bi = 0;
    for (int g = 0; g < G; g++) {
        float v = iou_f(gt[g * 4 + 0], gt[g * 4 + 1], gt[g * 4 + 2], gt[g * 4 + 3],
                        px1, py1, px2, py2);
        if (v > bv) { bv = v; bi = g; }   // strict > -> first max (jnp.argmax axis=0)
    }
    g_mval[idx] = bv;
    g_match[idx] = bi;
}

// ---------------- kernel 2: per-(b,g) argmax over priors ---------------------
__global__ void k_best_prior(const float* __restrict__ priors,
                             const float* __restrict__ gt_boxes,
                             int B, int P, int G) {
    int bg = blockIdx.x;            // b*G + g
    int b = bg / G, g = bg - b * G;
    int tid = threadIdx.x;
    const int NT = 256;
    __shared__ float sv[NT];
    __shared__ int   si[NT];

    const float* gt = gt_boxes + ((size_t)b * G + g) * 4;
    float gx1 = gt[0], gy1 = gt[1], gx2 = gt[2], gy2 = gt[3];

    float bv = -1.0f; int bi = 0x7FFFFFFF;
    for (int p = tid; p < P; p += NT) {
        float cx = priors[p * 4 + 0], cy = priors[p * 4 + 1];
        float w  = priors[p * 4 + 2], h  = priors[p * 4 + 3];
        float v = iou_f(gx1, gy1, gx2, gy2,
                        cx - w * 0.5f, cy - h * 0.5f, cx + w * 0.5f, cy + h * 0.5f);
        if (v > bv) { bv = v; bi = p; }   // within-thread: ascending scan keeps lowest p
    }
    sv[tid] = bv; si[tid] = bi;
    __syncthreads();
    for (int s = NT / 2; s > 0; s >>= 1) {
        if (tid < s) {
            float ov = sv[tid + s]; int oi = si[tid + s];
            if (ov > sv[tid] || (ov == sv[tid] && oi < si[tid])) { sv[tid] = ov; si[tid] = oi; }
        }
        __syncthreads();
    }
    if (tid == 0) g_bestp[bg] = si[0];
}

// ---------------- kernel 3: forced matches (sequential per batch) ------------
__global__ void k_force(int B, int P, int G) {
    int b = blockIdx.x * blockDim.x + threadIdx.x;
    if (b >= B) return;
    for (int g = 0; g < G; g++) {      // ascending: later g overwrites (scatter last-wins)
        int p = g_bestp[b * G + g];
        g_match[(size_t)b * P + p] = g;
        g_mval[(size_t)b * P + p] = 2.0f;
    }
}

// ---------------- kernel 4: fused softmax / CE / bg / smooth-L1 --------------
// one warp per (b,p) row, C <= 128
__global__ void k_main(const float* __restrict__ priors,
                       const float* __restrict__ logits,
                       const float* __restrict__ boxreg,
                       const float* __restrict__ gt_boxes,
                       const int*   __restrict__ gt_labels,
                       int B, int P, int C, int G) {
    int warp = (blockIdx.x * blockDim.x + threadIdx.x) >> 5;
    int lane = threadIdx.x & 31;
    int rows = B * P;
    if (warp >= rows) return;
    int b = warp / P, p = warp - b * P;

    const float* row = logits + (size_t)warp * C;
    float v0 = (lane      < C) ? row[lane]      : -INFINITY;
    float v1 = (lane + 32 < C) ? row[lane + 32] : -INFINITY;
    float v2 = (lane + 64 < C) ? row[lane + 64] : -INFINITY;
    float v3 = (lane + 96 < C) ? row[lane + 96] : -INFINITY;

    float mx = fmaxf(fmaxf(v0, v1), fmaxf(v2, v3));
    #pragma unroll
    for (int o = 16; o > 0; o >>= 1) mx = fmaxf(mx, __shfl_xor_sync(0xFFFFFFFFu, mx, o));

    float s = 0.0f;
    if (lane      < C) s += expf(v0 - mx);
    if (lane + 32 < C) s += expf(v1 - mx);
    if (lane + 64 < C) s += expf(v2 - mx);
    if (lane + 96 < C) s += expf(v3 - mx);
    #pragma unroll
    for (int o = 16; o > 0; o >>= 1) s += __shfl_xor_sync(0xFFFFFFFFu, s, o);
    float logZ = logf(s);

    float x0 = __shfl_sync(0xFFFFFFFFu, v0, 0);
    float bg = -(x0 - mx - logZ);

    float mval = g_mval[warp];
    int   m    = g_match[warp];
    int label = 0;
    if (mval >= 0.5f) label = gt_labels[b * G + m];
    bool pos = (label > 0);

    // gather logits[label] across the warp
    int slot = label >> 5;
    float vl = (slot == 0) ? v0 : (slot == 1) ? v1 : (slot == 2) ? v2 : v3;
    float lx = __shfl_sync(0xFFFFFFFFu, vl, label & 31);
    float ce = -(lx - mx - logZ);

    if (lane == 0) {
        g_bg[warp] = pos ? -INFINITY : bg;
        if (pos) {
            atomicAdd(&g_npos[b], 1);
            atomicAdd(&g_cesum, (double)ce);

            const float* gt = gt_boxes + ((size_t)b * G + m) * 4;
            float gx1 = gt[0], gy1 = gt[1], gx2 = gt[2], gy2 = gt[3];
            float ccx = (gx1 + gx2) * 0.5f, ccy = (gy1 + gy2) * 0.5f;
            float gw = gx2 - gx1, gh = gy2 - gy1;
            float pcx = priors[p * 4 + 0], pcy = priors[p * 4 + 1];
            float pw  = priors[p * 4 + 2], ph  = priors[p * 4 + 3];
            float t0 = (ccx - pcx) / (0.1f * pw);
            float t1 = (ccy - pcy) / (0.1f * ph);
            float t2 = logf(gw / pw) / 0.2f;
            float t3 = logf(gh / ph) / 0.2f;

            const float* br = boxreg + (size_t)warp * 4;
            float t[4] = {t0, t1, t2, t3};
            double sl = 0.0;
            #pragma unroll
            for (int i = 0; i < 4; i++) {
                float d = fabsf(br[i] - t[i]);
                sl += (d < 1.0f) ? (0.5f * d * d) : (d - 0.5f);
            }
            atomicAdd(&g_boxsum, sl);
        }
    }
}

// ---------------- kernel 5: per-batch top-k sum of negative bg_loss ----------
__global__ void k_topk(int B, int P) {
    __shared__ unsigned keys[MAXP];
    __shared__ int scnt;
    __shared__ double ssum;
    int b = blockIdx.x;
    int tid = threadIdx.x;
    int nt = blockDim.x;

    for (int p = tid; p < P; p += nt) keys[p] = f2k(g_bg[(size_t)b * P + p]);
    __syncthreads();

    int npos = g_npos[b];
    int nneg = P - npos;
    int k = 3 * npos;
    if (k > nneg) k = nneg;
    if (k <= 0) return;

    // binary search for k-th largest key: max K such that count(keys >= K) >= k
    unsigned lo = 0u, hi = 0xFFFFFFFFu;
    while (lo < hi) {
        unsigned mid = (unsigned)(((unsigned long long)lo + hi + 1ull) >> 1);
        if (tid == 0) scnt = 0;
        __syncthreads();
        int c = 0;
        for (int p = tid; p < P; p += nt) c += (keys[p] >= mid);
        #pragma unroll
        for (int o = 16; o > 0; o >>= 1) c += __shfl_down_sync(0xFFFFFFFFu, c, o);
        if ((tid & 31) == 0) atomicAdd(&scnt, c);
        __syncthreads();
        int cnt = scnt;
        __syncthreads();
        if (cnt >= k) lo = mid; else hi = mid - 1;
    }
    unsigned kth = lo;

    if (tid == 0) { scnt = 0; ssum = 0.0; }
    __syncthreads();
    int cg = 0; double s = 0.0;
    for (int p = tid; p < P; p += nt) {
        unsigned u = keys[p];
        if (u > kth) { cg++; s += (double)k2f(u); }
    }
    #pragma unroll
    for (int o = 16; o > 0; o >>= 1) {
        cg += __shfl_down_sync(0xFFFFFFFFu, cg, o);
        s  += __shfl_down_sync(0xFFFFFFFFu, s,  o);
    }
    if ((tid & 31) == 0) { atomicAdd(&scnt, cg); atomicAdd(&ssum, s); }
    __syncthreads();
    if (tid == 0) {
        double total = ssum + (double)(k - scnt) * (double)k2f(kth);
        atomicAdd(&g_cesum, total);
    }
}

// ---------------- kernel 6: finalize -----------------------------------------
__global__ void k_final(float* __restrict__ out, int B) {
    int np = 0;
    for (int b = 0; b < B; b++) np += g_npos[b];
    float n = (float)np;
    out[0] = (float)(g_boxsum / (double)n);
    out[1] = (float)(g_cesum  / (double)n);
}

// ---------------- launch -----------------------------------------------------
extern "C" void kernel_launch(void* const* d_in, const int* in_sizes, int n_in,
                              void* d_out, int out_size) {
    const float* priors    = (const float*)d_in[0];
    const float* logits    = (const float*)d_in[1];
    const float* boxreg    = (const float*)d_in[2];
    const float* gt_boxes  = (const float*)d_in[3];
    const int*   gt_labels = (const int*)  d_in[4];
    float* out = (float*)d_out;

    int P = in_sizes[0] / 4;
    int B = in_sizes[2] / (4 * P);
    int C = (int)((long long)in_sizes[1] / ((long long)B * P));
    int G = in_sizes[4] / B;

    k_init<<<1, 128>>>(B);

    int rows = B * P;
    k_match_rows<<<(rows + 255) / 256, 256>>>(priors, gt_boxes, B, P, G);
    k_best_prior<<<B * G, 256>>>(priors, gt_boxes, B, P, G);
    k_force<<<1, (B + 31) / 32 * 32>>>(B, P, G);

    int warps_per_block = 8;                 // 256 threads
    int nblk = (rows + warps_per_block - 1) / warps_per_block;
    k_main<<<nblk, warps_per_block * 32>>>(priors, logits, boxreg, gt_boxes, gt_labels,
                                           B, P, C, G);

    k_topk<<<B, 1024>>>(B, P);
    k_final<<<1, 1>>>(out, B);
    (void)n_in; (void)out_size;
}